// round 9
// baseline (speedup 1.0000x reference)
#include <cuda_runtime.h>
#include <cuda_fp16.h>
#include <cstdint>

// Scratch (no dynamic allocation allowed)
__device__ __half g_nf16[4096 * 256];     // fp16 projected features (gather source)
__device__ float  g_lp[4096 * 8];         // parent logits
__device__ float  g_lc[4096 * 8];         // child logits
__device__ float  g_u[256 * 16];          // u[k][hw] = sum_d W[h*32+d,k]*a[h, w*32+d]
__device__ float  g_beta[16];             // beta[hw] = sum_d b[h*32+d]*a[h, w*32+d]
__device__ float  g_xpart[32 * 256];      // x column-sum partials
__device__ float  g_total[256];           // column sum of nf (exact, from x)
__device__ int    g_cnt[4096];            // edges per row
__device__ int    g_ej[4096 * 512];       // compact edge lists

// ---------------------------------------------------------------------------
// Kernel 1: nf16 = fp16(x @ W^T + b)  — only the gather needs nf now.
// ---------------------------------------------------------------------------
__global__ __launch_bounds__(256) void gemm_kernel(const float* __restrict__ x,
                                                   const float* __restrict__ W,
                                                   const float* __restrict__ b) {
    __shared__ float As[16][68];
    __shared__ float Bs[16][68];
    int m0 = blockIdx.x * 64;
    int n0 = blockIdx.y * 64;
    int tx = threadIdx.x;
    int tm = tx >> 4, tn = tx & 15;
    float acc[4][4] = {};
    for (int k0 = 0; k0 < 256; k0 += 16) {
#pragma unroll
        for (int l = 0; l < 4; l++) {
            int idx = tx + l * 256;
            int r = idx >> 4;   // 0..63
            int k = idx & 15;   // 0..15
            As[k][r] = x[(m0 + r) * 256 + k0 + k];
            Bs[k][r] = W[(n0 + r) * 256 + k0 + k];
        }
        __syncthreads();
#pragma unroll
        for (int k = 0; k < 16; k++) {
            float4 av = *reinterpret_cast<const float4*>(&As[k][tm * 4]);
            float4 bv = *reinterpret_cast<const float4*>(&Bs[k][tn * 4]);
            acc[0][0] = fmaf(av.x, bv.x, acc[0][0]);
            acc[0][1] = fmaf(av.x, bv.y, acc[0][1]);
            acc[0][2] = fmaf(av.x, bv.z, acc[0][2]);
            acc[0][3] = fmaf(av.x, bv.w, acc[0][3]);
            acc[1][0] = fmaf(av.y, bv.x, acc[1][0]);
            acc[1][1] = fmaf(av.y, bv.y, acc[1][1]);
            acc[1][2] = fmaf(av.y, bv.z, acc[1][2]);
            acc[1][3] = fmaf(av.y, bv.w, acc[1][3]);
            acc[2][0] = fmaf(av.z, bv.x, acc[2][0]);
            acc[2][1] = fmaf(av.z, bv.y, acc[2][1]);
            acc[2][2] = fmaf(av.z, bv.z, acc[2][2]);
            acc[2][3] = fmaf(av.z, bv.w, acc[2][3]);
            acc[3][0] = fmaf(av.w, bv.x, acc[3][0]);
            acc[3][1] = fmaf(av.w, bv.y, acc[3][1]);
            acc[3][2] = fmaf(av.w, bv.z, acc[3][2]);
            acc[3][3] = fmaf(av.w, bv.w, acc[3][3]);
        }
        __syncthreads();
    }
#pragma unroll
    for (int i2 = 0; i2 < 4; i2++) {
        int row = m0 + tm * 4 + i2;
#pragma unroll
        for (int j2 = 0; j2 < 4; j2++) {
            int col = n0 + tn * 4 + j2;
            g_nf16[row * 256 + col] = __float2half(acc[i2][j2] + b[col]);
        }
    }
}

// ---------------------------------------------------------------------------
// Kernel U (side): u[k][hw] = sum_{d<32} W[h*32+d, k] * a[h, w*32+d]
//                  beta[hw] = sum_{d<32} b[h*32+d]   * a[h, w*32+d]
// ---------------------------------------------------------------------------
__global__ __launch_bounds__(256) void aW_kernel(const float* __restrict__ W,
                                                 const float* __restrict__ a,
                                                 const float* __restrict__ b) {
    int hw = blockIdx.x;        // 0..15
    int h = hw >> 1, w = hw & 1;
    int k = threadIdx.x;        // 0..255
    float u = 0.f;
#pragma unroll
    for (int d = 0; d < 32; d++)
        u = fmaf(W[(h * 32 + d) * 256 + k], a[h * 64 + w * 32 + d], u);
    g_u[k * 16 + hw] = u;
    if (k < 32) {
        float bb = b[h * 32 + k] * a[h * 64 + w * 32 + k];
#pragma unroll
        for (int o = 16; o > 0; o >>= 1) bb += __shfl_down_sync(0xffffffffu, bb, o);
        if (k == 0) g_beta[hw] = bb;
    }
}

// ---------------------------------------------------------------------------
// Kernel L (side): lp/lc = x @ u + beta  (fp32-exact logits, no nf needed)
// Block = 16 rows; thread (r, hw) does a 256-dot from smem.
// ---------------------------------------------------------------------------
__global__ __launch_bounds__(256) void lplc_kernel(const float* __restrict__ x) {
    __shared__ float s_x[16 * 256];
    __shared__ float s_u[256 * 16];
    int tid = threadIdx.x;
    int n0 = blockIdx.x * 16;
    for (int idx = tid; idx < 16 * 256; idx += 256) {
        s_x[idx] = x[n0 * 256 + idx];
        s_u[idx] = g_u[idx];
    }
    __syncthreads();
    int r = tid >> 4;           // row within chunk
    int hw = tid & 15;
    int h = hw >> 1, w = hw & 1;
    float dot = g_beta[hw];
#pragma unroll 8
    for (int k = 0; k < 256; k++)
        dot = fmaf(s_x[r * 256 + k], s_u[k * 16 + hw], dot);
    if (w == 0) g_lp[(n0 + r) * 8 + h] = dot;
    else        g_lc[(n0 + r) * 8 + h] = dot;
}

// ---------------------------------------------------------------------------
// Kernel 3 (side): g_total[c] = (sum_j x[j]) . W[c,:] + 4096*b[c]
// ---------------------------------------------------------------------------
__global__ __launch_bounds__(256) void xsum_kernel(const float* __restrict__ x) {
    int blk = blockIdx.x;   // 32 blocks, 128 rows each
    int t = threadIdx.x;
    float s = 0.f;
#pragma unroll 8
    for (int r = 0; r < 128; r++) s += x[(blk * 128 + r) * 256 + t];
    g_xpart[blk * 256 + t] = s;
}

__global__ __launch_bounds__(256) void total_kernel(const float* __restrict__ W,
                                                    const float* __restrict__ b) {
    __shared__ float s_xs[256];
    int t = threadIdx.x;
    int lane = t & 31;
    int wid = t >> 5;
    float s = 0.f;
#pragma unroll
    for (int r = 0; r < 32; r++) s += g_xpart[r * 256 + t];
    s_xs[t] = s;
    __syncthreads();
    int c = blockIdx.x * 8 + wid;   // one warp per output column
    float p = 0.f;
#pragma unroll
    for (int k = lane; k < 256; k += 32) p = fmaf(s_xs[k], W[c * 256 + k], p);
#pragma unroll
    for (int o = 16; o > 0; o >>= 1) p += __shfl_down_sync(0xffffffffu, p, o);
    if (lane == 0) g_total[c] = p + 4096.0f * b[c];
}

// ---------------------------------------------------------------------------
// Kernel S (side): adjacency prescan -> compact edge lists. Deterministic.
// ---------------------------------------------------------------------------
__global__ __launch_bounds__(256) void scan_kernel(const float* __restrict__ adj) {
    __shared__ int s_wsum[8];
    int i = blockIdx.x;
    int tid = threadIdx.x;
    int lane = tid & 31;
    int wid = tid >> 5;

    const float4* arow = (const float4*)(adj + (size_t)i * 4096);
    float4 q[4];
#pragma unroll
    for (int k = 0; k < 4; k++) q[k] = arow[k * 256 + tid];

    unsigned mask = 0;
#pragma unroll
    for (int k = 0; k < 4; k++) {
        mask |= (unsigned)(q[k].x != 0.f) << (k * 4 + 0);
        mask |= (unsigned)(q[k].y != 0.f) << (k * 4 + 1);
        mask |= (unsigned)(q[k].z != 0.f) << (k * 4 + 2);
        mask |= (unsigned)(q[k].w != 0.f) << (k * 4 + 3);
    }
    int lcount = __popc(mask);

    int scan = lcount;
#pragma unroll
    for (int o = 1; o < 32; o <<= 1) {
        int tt = __shfl_up_sync(0xffffffffu, scan, o);
        if (lane >= o) scan += tt;
    }
    if (lane == 31) s_wsum[wid] = scan;
    __syncthreads();

    int woff = 0, cnt = 0;
#pragma unroll
    for (int w = 0; w < 8; w++) {
        int s = s_wsum[w];
        cnt += s;
        if (w < wid) woff += s;
    }
    int pos = woff + scan - lcount;

    int* dst = g_ej + i * 512;
#pragma unroll
    for (int k = 0; k < 4; k++) {
        int jb = (k * 256 + tid) * 4;
        if ((mask >> (k * 4 + 0)) & 1) dst[pos++] = jb + 0;
        if ((mask >> (k * 4 + 1)) & 1) dst[pos++] = jb + 1;
        if ((mask >> (k * 4 + 2)) & 1) dst[pos++] = jb + 2;
        if ((mask >> (k * 4 + 3)) & 1) dst[pos++] = jb + 3;
    }
    if (tid == 0) g_cnt[i] = cnt;
}

// ---------------------------------------------------------------------------
// Kernel 4: gather-only aggregation, persistent blocks (no wave tail).
//   out[i,h,c] = (total[h,c] + sum_nbr (e-1)*nf[j,h,c]) / (4096 + sum_nbr (e-1))
// ---------------------------------------------------------------------------
#define MAXE 512
#define AGG_GRID 1184   // 148 SMs * 8 blocks

__global__ __launch_bounds__(256) void agg_kernel(float* __restrict__ out) {
    __shared__ int   s_j[MAXE];
    __shared__ float s_w[MAXE * 8];   // per-edge per-head weights; reused at end
    __shared__ float s_z[64];         // per-warp per-head zacc
    __shared__ float s_lp[8];

    int tid = threadIdx.x;
    int lane = tid & 31;
    int wid = tid >> 5;
    int hh = lane >> 2;               // head of this lane's 8 columns
    int c0 = lane * 8;

    for (int i = blockIdx.x; i < 4096; i += AGG_GRID) {
        int cnt = g_cnt[i];
        if (tid < 8) s_lp[tid] = g_lp[i * 8 + tid];
        for (int e = tid; e < cnt; e += 256) s_j[e] = g_ej[i * 512 + e];
        __syncthreads();

        // ---- dense weights: one exp per (edge, head) lane-slot ----
        int tot = cnt * 8;
        for (int idx = tid; idx < tot; idx += 256) {
            int e = idx >> 3;
            int h = idx & 7;
            int j = s_j[e];
            float l = s_lp[h] + __ldg(&g_lc[j * 8 + h]);
            l = l > 0.f ? l : 0.2f * l;
            s_w[idx] = __expf(l) - 1.f;
        }
        __syncthreads();

        // ---- accumulate (warp wid handles edges e%8==wid, 8 fp16 cols/lane) ----
        float a0 = 0.f, a1 = 0.f, a2 = 0.f, a3 = 0.f;
        float a4 = 0.f, a5 = 0.f, a6 = 0.f, a7 = 0.f;
        float zl = 0.f;

#pragma unroll 4
        for (int e = wid; e < cnt; e += 8) {
            int j = s_j[e];
            float w = s_w[e * 8 + hh];
            uint4 v = *(const uint4*)(&g_nf16[(size_t)j * 256 + c0]);
            float2 f0 = __half22float2(*(__half2*)&v.x);
            float2 f1 = __half22float2(*(__half2*)&v.y);
            float2 f2 = __half22float2(*(__half2*)&v.z);
            float2 f3 = __half22float2(*(__half2*)&v.w);
            a0 = fmaf(w, f0.x, a0);
            a1 = fmaf(w, f0.y, a1);
            a2 = fmaf(w, f1.x, a2);
            a3 = fmaf(w, f1.y, a3);
            a4 = fmaf(w, f2.x, a4);
            a5 = fmaf(w, f2.y, a5);
            a6 = fmaf(w, f3.x, a6);
            a7 = fmaf(w, f3.y, a7);
            zl += w;
        }
        __syncthreads();   // s_w reuse below

        // ---- combine 8 warps' partials (reuse s_w as scratch) ----
        float* s_acc = s_w;
        *(float4*)(&s_acc[wid * 256 + c0])     = make_float4(a0, a1, a2, a3);
        *(float4*)(&s_acc[wid * 256 + c0 + 4]) = make_float4(a4, a5, a6, a7);
        if ((lane & 3) == 0) s_z[wid * 8 + hh] = zl;
        __syncthreads();

        int c = tid;
        int h = c >> 5;
        float r = g_total[c];
        float z = 0.f;
#pragma unroll
        for (int w = 0; w < 8; w++) {
            r += s_acc[w * 256 + c];
            z += s_z[w * 8 + h];
        }
        out[(size_t)i * 256 + c] = r / (4096.0f + z);
        __syncthreads();   // protect s_w/s_lp before next iteration
    }
}

// ---------------------------------------------------------------------------
// Side streams + events: created LAZILY on the first (non-captured) call.
// Host-side objects only — no device memory.
// ---------------------------------------------------------------------------
namespace {
struct SideStreams {
    cudaStream_t s2 = nullptr, s3 = nullptr;
    cudaEvent_t eRoot = nullptr, eB = nullptr, eC = nullptr;
    bool ok = false;
    bool tried = false;
    void init() {
        if (tried) return;
        tried = true;
        ok = cudaStreamCreateWithFlags(&s2, cudaStreamNonBlocking) == cudaSuccess &&
             cudaStreamCreateWithFlags(&s3, cudaStreamNonBlocking) == cudaSuccess &&
             cudaEventCreateWithFlags(&eRoot, cudaEventDisableTiming) == cudaSuccess &&
             cudaEventCreateWithFlags(&eB, cudaEventDisableTiming) == cudaSuccess &&
             cudaEventCreateWithFlags(&eC, cudaEventDisableTiming) == cudaSuccess;
    }
};
SideStreams g_ss;   // constructor does NOT touch CUDA
}

extern "C" void kernel_launch(void* const* d_in, const int* in_sizes, int n_in,
                              void* d_out, int out_size) {
    const float* x   = (const float*)d_in[0];   // [4096,256]
    const float* W   = (const float*)d_in[1];   // [256,256]
    const float* b   = (const float*)d_in[2];   // [256]
    const float* a   = (const float*)d_in[3];   // [8,64]
    const float* adj = (const float*)d_in[4];   // [4096,4096]
    float* out = (float*)d_out;                 // [4096,256]

    cudaStreamCaptureStatus cap = cudaStreamCaptureStatusNone;
    cudaStreamIsCapturing(0, &cap);
    if (!g_ss.tried && cap == cudaStreamCaptureStatusNone) g_ss.init();

    if (g_ss.ok) {
        cudaEventRecord(g_ss.eRoot, 0);
        cudaStreamWaitEvent(g_ss.s2, g_ss.eRoot, 0);
        cudaStreamWaitEvent(g_ss.s3, g_ss.eRoot, 0);

        // critical path: gemm -> agg
        gemm_kernel<<<dim3(64, 4), 256>>>(x, W, b);

        // side chain A: logits from x (exact) + total from x
        aW_kernel<<<16, 256, 0, g_ss.s2>>>(W, a, b);
        lplc_kernel<<<256, 256, 0, g_ss.s2>>>(x);
        xsum_kernel<<<32, 256, 0, g_ss.s2>>>(x);
        total_kernel<<<32, 256, 0, g_ss.s2>>>(W, b);

        // side chain B: adjacency compaction
        scan_kernel<<<4096, 256, 0, g_ss.s3>>>(adj);

        cudaEventRecord(g_ss.eB, g_ss.s2);
        cudaEventRecord(g_ss.eC, g_ss.s3);
        cudaStreamWaitEvent(0, g_ss.eB, 0);
        cudaStreamWaitEvent(0, g_ss.eC, 0);

        agg_kernel<<<AGG_GRID, 256>>>(out);
    } else {
        gemm_kernel<<<dim3(64, 4), 256>>>(x, W, b);
        aW_kernel<<<16, 256>>>(W, a, b);
        lplc_kernel<<<256, 256>>>(x);
        xsum_kernel<<<32, 256>>>(x);
        total_kernel<<<32, 256>>>(W, b);
        scan_kernel<<<4096, 256>>>(adj);
        agg_kernel<<<AGG_GRID, 256>>>(out);
    }
}

// round 11
// speedup vs baseline: 1.2521x; 1.2521x over previous
#include <cuda_runtime.h>
#include <cuda_fp16.h>
#include <cstdint>

// Scratch (no dynamic allocation allowed)
__device__ __half g_nf16[4096 * 256];     // fp16 projected features (gather source)
__device__ float  g_lp[4096 * 8];         // parent logits (exact fp32)
__device__ float  g_lc[4096 * 8];         // child logits (exact fp32)
__device__ float  g_xpart[128 * 256];     // x column-sum partials
__device__ float  g_total[256];           // column sum of nf (exact, from x)
__device__ int    g_cnt[4096];            // edges per row
__device__ int    g_ej[4096 * 512];       // compact edge lists

// ---------------------------------------------------------------------------
// Kernel 1: nf16 = fp16(x @ W^T + b), with FUSED exact fp32 logits.
// Block covers rows m0..m0+63, cols n0..n0+63 (= heads 2ny, 2ny+1), so each
// (row, head) is fully owned by one block: no cross-block reduction.
// ---------------------------------------------------------------------------
__global__ __launch_bounds__(256) void gemm_kernel(const float* __restrict__ x,
                                                   const float* __restrict__ W,
                                                   const float* __restrict__ b,
                                                   const float* __restrict__ a) {
    __shared__ float As[16][68];
    __shared__ float Bs[16][68];
    __shared__ float s_a[2][64];   // a-rows for this tile's 2 heads
    int m0 = blockIdx.x * 64;
    int n0 = blockIdx.y * 64;
    int tx = threadIdx.x;
    int tm = tx >> 4, tn = tx & 15;

    if (tx < 128) s_a[tx >> 6][tx & 63] = a[(2 * blockIdx.y) * 64 + tx];

    float acc[4][4] = {};
    for (int k0 = 0; k0 < 256; k0 += 16) {
#pragma unroll
        for (int l = 0; l < 4; l++) {
            int idx = tx + l * 256;
            int r = idx >> 4;   // 0..63
            int k = idx & 15;   // 0..15
            As[k][r] = x[(m0 + r) * 256 + k0 + k];
            Bs[k][r] = W[(n0 + r) * 256 + k0 + k];
        }
        __syncthreads();
#pragma unroll
        for (int k = 0; k < 16; k++) {
            float4 av = *reinterpret_cast<const float4*>(&As[k][tm * 4]);
            float4 bv = *reinterpret_cast<const float4*>(&Bs[k][tn * 4]);
            acc[0][0] = fmaf(av.x, bv.x, acc[0][0]);
            acc[0][1] = fmaf(av.x, bv.y, acc[0][1]);
            acc[0][2] = fmaf(av.x, bv.z, acc[0][2]);
            acc[0][3] = fmaf(av.x, bv.w, acc[0][3]);
            acc[1][0] = fmaf(av.y, bv.x, acc[1][0]);
            acc[1][1] = fmaf(av.y, bv.y, acc[1][1]);
            acc[1][2] = fmaf(av.y, bv.z, acc[1][2]);
            acc[1][3] = fmaf(av.y, bv.w, acc[1][3]);
            acc[2][0] = fmaf(av.z, bv.x, acc[2][0]);
            acc[2][1] = fmaf(av.z, bv.y, acc[2][1]);
            acc[2][2] = fmaf(av.z, bv.z, acc[2][2]);
            acc[2][3] = fmaf(av.z, bv.w, acc[2][3]);
            acc[3][0] = fmaf(av.w, bv.x, acc[3][0]);
            acc[3][1] = fmaf(av.w, bv.y, acc[3][1]);
            acc[3][2] = fmaf(av.w, bv.z, acc[3][2]);
            acc[3][3] = fmaf(av.w, bv.w, acc[3][3]);
        }
        __syncthreads();
    }

    // biased values vv = nf (exact fp32)
    float vv[4][4];
    float4 bb = *reinterpret_cast<const float4*>(&b[n0 + tn * 4]);
    float bs[4] = {bb.x, bb.y, bb.z, bb.w};
#pragma unroll
    for (int i2 = 0; i2 < 4; i2++) {
        int row = m0 + tm * 4 + i2;
#pragma unroll
        for (int j2 = 0; j2 < 4; j2++) {
            float v = acc[i2][j2] + bs[j2];
            vv[i2][j2] = v;
            g_nf16[row * 256 + n0 + tn * 4 + j2] = __float2half(v);
        }
    }

    // fused logits: per-thread partials over its 4 cols (one head), then
    // 3-step xor-shuffle tree across the 8 tn-threads of this head group.
    int hd = tn >> 3;                    // head within tile (0/1)
    int dbase = tn * 4 - hd * 32;        // d of first owned col (0..28)
    float lpv[4], lcv[4];
#pragma unroll
    for (int i2 = 0; i2 < 4; i2++) {
        float lp_ = 0.f, lc_ = 0.f;
#pragma unroll
        for (int j2 = 0; j2 < 4; j2++) {
            lp_ = fmaf(vv[i2][j2], s_a[hd][dbase + j2], lp_);
            lc_ = fmaf(vv[i2][j2], s_a[hd][32 + dbase + j2], lc_);
        }
        lpv[i2] = lp_;
        lcv[i2] = lc_;
    }
#pragma unroll
    for (int o = 1; o < 8; o <<= 1) {
#pragma unroll
        for (int i2 = 0; i2 < 4; i2++) {
            lpv[i2] += __shfl_xor_sync(0xffffffffu, lpv[i2], o);
            lcv[i2] += __shfl_xor_sync(0xffffffffu, lcv[i2], o);
        }
    }
    if ((tn & 7) == 0) {
        int h = 2 * blockIdx.y + hd;
#pragma unroll
        for (int i2 = 0; i2 < 4; i2++) {
            int row = m0 + tm * 4 + i2;
            g_lp[row * 8 + h] = lpv[i2];
            g_lc[row * 8 + h] = lcv[i2];
        }
    }
}

// ---------------------------------------------------------------------------
// Kernel 3 (side): g_total[c] = (sum_j x[j]) . W[c,:] + 4096*b[c]
// ---------------------------------------------------------------------------
__global__ __launch_bounds__(256) void xsum_kernel(const float* __restrict__ x) {
    int blk = blockIdx.x;   // 128 blocks, 32 rows each
    int t = threadIdx.x;
    float s = 0.f;
#pragma unroll 8
    for (int r = 0; r < 32; r++) s += x[(blk * 32 + r) * 256 + t];
    g_xpart[blk * 256 + t] = s;
}

__global__ __launch_bounds__(256) void total_kernel(const float* __restrict__ W,
                                                    const float* __restrict__ b) {
    __shared__ float s_xs[256];
    int t = threadIdx.x;
    int lane = t & 31;
    int wid = t >> 5;
    float s = 0.f;
#pragma unroll 8
    for (int r = 0; r < 128; r++) s += g_xpart[r * 256 + t];
    s_xs[t] = s;
    __syncthreads();
    int c = blockIdx.x * 8 + wid;   // one warp per output column
    float p = 0.f;
#pragma unroll
    for (int k = lane; k < 256; k += 32) p = fmaf(s_xs[k], W[c * 256 + k], p);
#pragma unroll
    for (int o = 16; o > 0; o >>= 1) p += __shfl_down_sync(0xffffffffu, p, o);
    if (lane == 0) g_total[c] = p + 4096.0f * b[c];
}

// ---------------------------------------------------------------------------
// Kernel S (side): adjacency prescan -> compact edge lists. Deterministic.
// ---------------------------------------------------------------------------
__global__ __launch_bounds__(256) void scan_kernel(const float* __restrict__ adj) {
    __shared__ int s_wsum[8];
    int i = blockIdx.x;
    int tid = threadIdx.x;
    int lane = tid & 31;
    int wid = tid >> 5;

    const float4* arow = (const float4*)(adj + (size_t)i * 4096);
    float4 q[4];
#pragma unroll
    for (int k = 0; k < 4; k++) q[k] = arow[k * 256 + tid];

    unsigned mask = 0;
#pragma unroll
    for (int k = 0; k < 4; k++) {
        mask |= (unsigned)(q[k].x != 0.f) << (k * 4 + 0);
        mask |= (unsigned)(q[k].y != 0.f) << (k * 4 + 1);
        mask |= (unsigned)(q[k].z != 0.f) << (k * 4 + 2);
        mask |= (unsigned)(q[k].w != 0.f) << (k * 4 + 3);
    }
    int lcount = __popc(mask);

    int scan = lcount;
#pragma unroll
    for (int o = 1; o < 32; o <<= 1) {
        int tt = __shfl_up_sync(0xffffffffu, scan, o);
        if (lane >= o) scan += tt;
    }
    if (lane == 31) s_wsum[wid] = scan;
    __syncthreads();

    int woff = 0, cnt = 0;
#pragma unroll
    for (int w = 0; w < 8; w++) {
        int s = s_wsum[w];
        cnt += s;
        if (w < wid) woff += s;
    }
    int pos = woff + scan - lcount;

    int* dst = g_ej + i * 512;
#pragma unroll
    for (int k = 0; k < 4; k++) {
        int jb = (k * 256 + tid) * 4;
        if ((mask >> (k * 4 + 0)) & 1) dst[pos++] = jb + 0;
        if ((mask >> (k * 4 + 1)) & 1) dst[pos++] = jb + 1;
        if ((mask >> (k * 4 + 2)) & 1) dst[pos++] = jb + 2;
        if ((mask >> (k * 4 + 3)) & 1) dst[pos++] = jb + 3;
    }
    if (tid == 0) g_cnt[i] = cnt;
}

// ---------------------------------------------------------------------------
// Kernel 4: gather-only aggregation, persistent blocks.
//   out[i,h,c] = (total[h,c] + sum_nbr (e-1)*nf[j,h,c]) / (4096 + sum_nbr (e-1))
// ---------------------------------------------------------------------------
#define MAXE 512
#define AGG_GRID 1184   // 148 SMs * 8 blocks

__global__ __launch_bounds__(256) void agg_kernel(float* __restrict__ out) {
    __shared__ int   s_j[MAXE];
    __shared__ float s_w[MAXE * 8];   // per-edge per-head weights; reused at end
    __shared__ float s_z[64];         // per-warp per-head zacc
    __shared__ float s_lp[8];

    int tid = threadIdx.x;
    int lane = tid & 31;
    int wid = tid >> 5;
    int hh = lane >> 2;               // head of this lane's 8 columns
    int c0 = lane * 8;

    for (int i = blockIdx.x; i < 4096; i += AGG_GRID) {
        int cnt = g_cnt[i];
        if (tid < 8) s_lp[tid] = g_lp[i * 8 + tid];
        for (int e = tid; e < cnt; e += 256) s_j[e] = g_ej[i * 512 + e];
        __syncthreads();

        // ---- dense weights: one exp per (edge, head) lane-slot ----
        int tot = cnt * 8;
        for (int idx = tid; idx < tot; idx += 256) {
            int e = idx >> 3;
            int h = idx & 7;
            int j = s_j[e];
            float l = s_lp[h] + __ldg(&g_lc[j * 8 + h]);
            l = l > 0.f ? l : 0.2f * l;
            s_w[idx] = __expf(l) - 1.f;
        }
        __syncthreads();

        // ---- accumulate (warp wid handles edges e%8==wid, 8 fp16 cols/lane) ----
        float a0 = 0.f, a1 = 0.f, a2 = 0.f, a3 = 0.f;
        float a4 = 0.f, a5 = 0.f, a6 = 0.f, a7 = 0.f;
        float zl = 0.f;

#pragma unroll 4
        for (int e = wid; e < cnt; e += 8) {
            int j = s_j[e];
            float w = s_w[e * 8 + hh];
            uint4 v = *(const uint4*)(&g_nf16[(size_t)j * 256 + c0]);
            float2 f0 = __half22float2(*(__half2*)&v.x);
            float2 f1 = __half22float2(*(__half2*)&v.y);
            float2 f2 = __half22float2(*(__half2*)&v.z);
            float2 f3 = __half22float2(*(__half2*)&v.w);
            a0 = fmaf(w, f0.x, a0);
            a1 = fmaf(w, f0.y, a1);
            a2 = fmaf(w, f1.x, a2);
            a3 = fmaf(w, f1.y, a3);
            a4 = fmaf(w, f2.x, a4);
            a5 = fmaf(w, f2.y, a5);
            a6 = fmaf(w, f3.x, a6);
            a7 = fmaf(w, f3.y, a7);
            zl += w;
        }
        __syncthreads();   // s_w reuse below

        // ---- combine 8 warps' partials (reuse s_w as scratch) ----
        float* s_acc = s_w;
        *(float4*)(&s_acc[wid * 256 + c0])     = make_float4(a0, a1, a2, a3);
        *(float4*)(&s_acc[wid * 256 + c0 + 4]) = make_float4(a4, a5, a6, a7);
        if ((lane & 3) == 0) s_z[wid * 8 + hh] = zl;
        __syncthreads();

        int c = tid;
        int h = c >> 5;
        float r = g_total[c];
        float z = 0.f;
#pragma unroll
        for (int w = 0; w < 8; w++) {
            r += s_acc[w * 256 + c];
            z += s_z[w * 8 + h];
        }
        out[(size_t)i * 256 + c] = r / (4096.0f + z);
        __syncthreads();   // protect s_w/s_lp before next iteration
    }
}

// ---------------------------------------------------------------------------
// Side streams + events: created LAZILY on the first (non-captured) call.
// Host-side objects only — no device memory.
// ---------------------------------------------------------------------------
namespace {
struct SideStreams {
    cudaStream_t s2 = nullptr, s3 = nullptr;
    cudaEvent_t eRoot = nullptr, eB = nullptr, eC = nullptr;
    bool ok = false;
    bool tried = false;
    void init() {
        if (tried) return;
        tried = true;
        ok = cudaStreamCreateWithFlags(&s2, cudaStreamNonBlocking) == cudaSuccess &&
             cudaStreamCreateWithFlags(&s3, cudaStreamNonBlocking) == cudaSuccess &&
             cudaEventCreateWithFlags(&eRoot, cudaEventDisableTiming) == cudaSuccess &&
             cudaEventCreateWithFlags(&eB, cudaEventDisableTiming) == cudaSuccess &&
             cudaEventCreateWithFlags(&eC, cudaEventDisableTiming) == cudaSuccess;
    }
};
SideStreams g_ss;   // constructor does NOT touch CUDA
}

extern "C" void kernel_launch(void* const* d_in, const int* in_sizes, int n_in,
                              void* d_out, int out_size) {
    const float* x   = (const float*)d_in[0];   // [4096,256]
    const float* W   = (const float*)d_in[1];   // [256,256]
    const float* b   = (const float*)d_in[2];   // [256]
    const float* a   = (const float*)d_in[3];   // [8,64]
    const float* adj = (const float*)d_in[4];   // [4096,4096]
    float* out = (float*)d_out;                 // [4096,256]

    cudaStreamCaptureStatus cap = cudaStreamCaptureStatusNone;
    cudaStreamIsCapturing(0, &cap);
    if (!g_ss.tried && cap == cudaStreamCaptureStatusNone) g_ss.init();

    if (g_ss.ok) {
        cudaEventRecord(g_ss.eRoot, 0);
        cudaStreamWaitEvent(g_ss.s2, g_ss.eRoot, 0);
        cudaStreamWaitEvent(g_ss.s3, g_ss.eRoot, 0);

        // critical path: gemm (with fused logits) -> agg
        gemm_kernel<<<dim3(64, 4), 256>>>(x, W, b, a);

        // side chain A: total from x (short!)
        xsum_kernel<<<128, 256, 0, g_ss.s2>>>(x);
        total_kernel<<<32, 256, 0, g_ss.s2>>>(W, b);

        // side chain B: adjacency compaction
        scan_kernel<<<4096, 256, 0, g_ss.s3>>>(adj);

        cudaEventRecord(g_ss.eB, g_ss.s2);
        cudaEventRecord(g_ss.eC, g_ss.s3);
        cudaStreamWaitEvent(0, g_ss.eB, 0);
        cudaStreamWaitEvent(0, g_ss.eC, 0);

        agg_kernel<<<AGG_GRID, 256>>>(out);
    } else {
        gemm_kernel<<<dim3(64, 4), 256>>>(x, W, b, a);
        xsum_kernel<<<128, 256>>>(x);
        total_kernel<<<32, 256>>>(W, b);
        scan_kernel<<<4096, 256>>>(adj);
        agg_kernel<<<AGG_GRID, 256>>>(out);
    }
}